// round 17
// baseline (speedup 1.0000x reference)
#include <cuda_runtime.h>
#include <cstdint>

// Problem constants
#define B_TOTAL 1024
#define T_PRED  24
#define FEAT    15
#define FILT    64
#define LENC    168
#define NDIL    6

// Kernel config
#define BROWS   8
#define NBLK    (B_TOTAL / BROWS)   // 128
#define NT      256
#define KW      68    // padded row stride (floats) for transposed weights

typedef unsigned long long u64;

static __device__ __forceinline__ float fast_tanh(float x) {
    float e;
    asm("ex2.approx.f32 %0, %1;" : "=f"(e) : "f"(x * 2.8853900817779268f));
    float r;
    asm("rcp.approx.f32 %0, %1;" : "=f"(r) : "f"(e + 1.0f));
    return fmaf(-2.0f, r, 1.0f);
}
static __device__ __forceinline__ float fast_sigmoid(float x) {
    float e;
    asm("ex2.approx.f32 %0, %1;" : "=f"(e) : "f"(-x * 1.4426950408889634f));
    float r;
    asm("rcp.approx.f32 %0, %1;" : "=f"(r) : "f"(e + 1.0f));
    return r;
}

// packed f32x2 helpers
static __device__ __forceinline__ void fma2(u64& d, u64 a, u64 b) {
    asm("fma.rn.f32x2 %0, %1, %2, %0;" : "+l"(d) : "l"(a), "l"(b));
}
static __device__ __forceinline__ float sum2(u64 v) {
    float lo, hi; asm("mov.b64 {%0, %1}, %2;" : "=f"(lo), "=f"(hi) : "l"(v));
    return lo + hi;
}

// W5 pre-packed: [kpair][col][parity]  (parity = k & 1)
__device__ float g_W5P[384 * 128];

__global__ void w5_pack_kernel(const float* __restrict__ gW5) {
    int e = blockIdx.x * blockDim.x + threadIdx.x;
    if (e < 384 * 128) {
        int k = e >> 7, c = e & 127;
        g_W5P[(k >> 1) * 256 + c * 2 + (k & 1)] = gW5[e];
    }
}

// ---- shared memory layout (float offsets) ----
#define OFF_W2T  0
#define OFF_W3T  (128*KW)
#define OFF_W4T  (2*128*KW)
#define OFF_W1   (3*128*KW)
#define OFF_W6   (OFF_W1 + 1024)
#define OFF_B1   (OFF_W6 + 128)
#define OFF_B2   (OFF_B1 + 64)
#define OFF_B4   (OFF_B2 + 128)
#define OFF_B5   (OFF_B4 + 128)
#define OFF_B6   (OFF_B5 + 128)
#define OFF_RING (OFF_B6 + 8)          // 31 slices * 512 floats
#define OFF_ENC5 (OFF_RING + 31*512)
#define OFF_INP  (OFF_ENC5 + 512)
#define OFF_GAT  (OFF_INP + 512)
#define OFF_CUR  (OFF_GAT + 512)
#define OFF_SKP  (OFF_CUR + 128)       // skip [row*384 + i*64 + j]
#define OFF_WP   (OFF_SKP + 8*384)     // W5 partials [ks*1024 + r*128 + c]
#define OFF_H    (OFF_WP + 4096)
#define OFF_PV   (OFF_H + 1024)
#define SMEM_FLOATS (OFF_PV + 8)

__global__ __launch_bounds__(NT, 1)
void decoder_kernel(const float* __restrict__ feat,   // (1024, 24, 15)
                    const float* __restrict__ init,   // (1024, 1)
                    const float* __restrict__ enc,    // (6, 1024, 168, 64)
                    const float* __restrict__ gW1, const float* __restrict__ gb1,
                    const float* __restrict__ gW2, const float* __restrict__ gb2,
                    const float* __restrict__ gW3,
                    const float* __restrict__ gW4, const float* __restrict__ gb4,
                    const float* __restrict__ gb5,
                    const float* __restrict__ gW6, const float* __restrict__ gb6,
                    float* __restrict__ out)          // (1024, 24)
{
    extern __shared__ float sm[];
    float* const ring = sm + OFF_RING;
    float* const enc5 = sm + OFF_ENC5;
    float* const inp  = sm + OFF_INP;
    float* const gat  = sm + OFF_GAT;
    float* const cur  = sm + OFF_CUR;
    float* const skp  = sm + OFF_SKP;
    float* const wp   = sm + OFF_WP;
    float* const hsm  = sm + OFF_H;
    float* const pv   = sm + OFF_PV;

    const int tid  = threadIdx.x;
    const int row0 = blockIdx.x * BROWS;

    // ---- one-time: load + transpose weights into smem ----
    for (int idx = tid; idx < 8192; idx += NT) {
        int k = idx >> 7, c = idx & 127;
        sm[OFF_W2T + c*KW + k] = gW2[idx];
        sm[OFF_W3T + c*KW + k] = gW3[idx];
        sm[OFF_W4T + c*KW + k] = gW4[idx];
    }
    for (int idx = tid; idx < 1024; idx += NT) sm[OFF_W1 + idx] = gW1[idx];
    if (tid < 128) {
        sm[OFF_W6 + tid] = gW6[tid];
        sm[OFF_B2 + tid] = gb2[tid];
        sm[OFF_B4 + tid] = gb4[tid];
        sm[OFF_B5 + tid] = gb5[tid];
    }
    if (tid >= 128 && tid < 192) sm[OFF_B1 + tid - 128] = gb1[tid - 128];
    if (tid == 224) sm[OFF_B6] = gb6[0];
    if (tid >= 240 && tid < 248) pv[tid - 240] = init[row0 + tid - 240];
    __syncthreads();

    // ---- stage-phase thread mapping: j2 = col pair (j2, j2+64), kg = k-segment of 16 ----
    const int j2 = tid >> 2;     // 0..63
    const int kg = tid & 3;      // 0..3 (== lane & 3 -> shfl-reducible)

    // ---- persistent weight registers: 16 k x {W2,W3,W4} x {colA, colB} as f32x2 pairs ----
    u64 W2A[8], W2B[8], W3A[8], W3B[8], W4A[8], W4B[8];
    {
        const float* p2a = sm + OFF_W2T + j2*KW + kg*16;
        const float* p2b = sm + OFF_W2T + (j2+64)*KW + kg*16;
        const float* p3a = sm + OFF_W3T + j2*KW + kg*16;
        const float* p3b = sm + OFF_W3T + (j2+64)*KW + kg*16;
        const float* p4a = sm + OFF_W4T + j2*KW + kg*16;
        const float* p4b = sm + OFF_W4T + (j2+64)*KW + kg*16;
        #pragma unroll
        for (int m = 0; m < 8; m++) {
            W2A[m] = *(const u64*)(p2a + 2*m);
            W2B[m] = *(const u64*)(p2b + 2*m);
            W3A[m] = *(const u64*)(p3a + 2*m);
            W3B[m] = *(const u64*)(p3b + 2*m);
            W4A[m] = *(const u64*)(p4a + 2*m);
            W4B[m] = *(const u64*)(p4b + 2*m);
        }
    }
    const float bb2f = sm[OFF_B2 + j2], bb2g = sm[OFF_B2 + 64 + j2];
    const float bb4s = sm[OFF_B4 + j2], bb4r = sm[OFF_B4 + 64 + j2];

    // enc5 (d=32) prefetch registers: 2 elements per thread
    #define ENC5_ADDR(o_, t_) \
        ((((size_t)5*B_TOTAL + row0 + ((o_) >> 6))*LENC + (LENC + (t_) - 32))*FILT + ((o_) & 63))
    float pf0 = enc[ENC5_ADDR(tid,       0)];
    float pf1 = enc[ENC5_ADDR(tid + 256, 0)];

    for (int t = 0; t < T_PRED; t++) {
        // ---- Phase A: stage enc slices + cur ----
        enc5[tid]       = pf0;
        enc5[tid + 256] = pf1;
        #pragma unroll
        for (int i = 0; i < 5; i++) {
            const int d = 1 << i;
            if (t < d) {
                const int sl = (d - 1) + (t & (d - 1));
                #pragma unroll
                for (int o = tid; o < 512; o += NT) {
                    int rg = o >> 6, k = o & 63;
                    ring[sl*512 + o] =
                        enc[(((size_t)i*B_TOTAL + row0 + rg)*LENC + (LENC + t - d))*FILT + k];
                }
            }
        }
        if (tid < 128) {
            int r = tid >> 4, c = tid & 15;
            cur[tid] = (c == 0) ? pv[r]
                                : feat[(size_t)(row0 + r)*T_PRED*FEAT + t*FEAT + (c - 1)];
        }
        __syncthreads();

        // ---- Phase B: inputs = tanh(cur @ W1 + b1) ----
        #pragma unroll
        for (int o = tid; o < 512; o += NT) {
            int rg = o >> 6, jj = o & 63;
            float acc = sm[OFF_B1 + jj];
            #pragma unroll
            for (int k = 0; k < 16; k++)
                acc = fmaf(cur[rg*16 + k], sm[OFF_W1 + k*64 + jj], acc);
            inp[o] = fast_tanh(acc);
        }
        __syncthreads();

        // ---- dilation stages: 256 threads, weights in registers, shfl kg-reduction ----
        #pragma unroll 1
        for (int i = 0; i < NDIL; i++) {
            const int d  = 1 << i;
            const int sl = (d - 1) + (t & (d - 1));
            const float* base = (i < 5) ? (ring + sl*512) : enc5;

            // phase 1: k-partial F/G for all 8 rows
            float fr[8], gr[8];
            #pragma unroll
            for (int r = 0; r < 8; r++) {
                const float* srow = base + r*64 + kg*16;
                const float* irow = inp  + r*64 + kg*16;
                u64 F = 0ull, G = 0ull;
                #pragma unroll
                for (int m = 0; m < 8; m++) {
                    u64 sv = *(const u64*)(srow + 2*m);
                    u64 iv = *(const u64*)(irow + 2*m);
                    fma2(F, sv, W2A[m]);
                    fma2(F, iv, W3A[m]);
                    fma2(G, sv, W2B[m]);
                    fma2(G, iv, W3B[m]);
                }
                fr[r] = sum2(F);
                gr[r] = sum2(G);
            }
            #pragma unroll
            for (int r = 0; r < 8; r++) {
                fr[r] += __shfl_xor_sync(0xffffffffu, fr[r], 1);
                fr[r] += __shfl_xor_sync(0xffffffffu, fr[r], 2);
                gr[r] += __shfl_xor_sync(0xffffffffu, gr[r], 1);
                gr[r] += __shfl_xor_sync(0xffffffffu, gr[r], 2);
            }
            if (kg == 0) {
                #pragma unroll
                for (int r = 0; r < 8; r++)
                    gat[r*64 + j2] = fast_tanh(fr[r] + bb2f) * fast_sigmoid(gr[r] + bb2g);
            }
            __syncthreads();

            // phase 2: gated @ W4 -> skips / residuals
            float sr[8], rr[8];
            #pragma unroll
            for (int r = 0; r < 8; r++) {
                const float* grow = gat + r*64 + kg*16;
                u64 S = 0ull, R = 0ull;
                #pragma unroll
                for (int m = 0; m < 8; m++) {
                    u64 gv = *(const u64*)(grow + 2*m);
                    fma2(S, gv, W4A[m]);
                    fma2(R, gv, W4B[m]);
                }
                sr[r] = sum2(S);
                rr[r] = sum2(R);
            }
            #pragma unroll
            for (int r = 0; r < 8; r++) {
                sr[r] += __shfl_xor_sync(0xffffffffu, sr[r], 1);
                sr[r] += __shfl_xor_sync(0xffffffffu, sr[r], 2);
                rr[r] += __shfl_xor_sync(0xffffffffu, rr[r], 1);
                rr[r] += __shfl_xor_sync(0xffffffffu, rr[r], 2);
            }
            if (kg == 0) {
                float* slot = ring + sl*512;
                #pragma unroll
                for (int r = 0; r < 8; r++) {
                    const int e = r*64 + j2;
                    float ni = inp[e] + (rr[r] + bb4r);
                    skp[r*384 + i*64 + j2] = fmaxf(sr[r] + bb4s, 0.0f);
                    if (i < 5) slot[e] = ni;
                    inp[e] = ni;
                }
            }
            __syncthreads();
        }

        // prefetch next step's enc5 slice (latency hidden under Phase E)
        if (t + 1 < T_PRED) {
            pf0 = enc[ENC5_ADDR(tid,       t + 1)];
            pf1 = enc[ENC5_ADDR(tid + 256, t + 1)];
        }

        // ---- Phase E: skip @ W5 (256 threads: 64 col-pairs x 4 k-segments, FFMA2) ----
        {
            const int q  = tid & 63;      // cols 2q, 2q+1
            const int ks = tid >> 6;      // k-segment (96 k = 48 kpairs each)
            const u64* w5p = (const u64*)g_W5P;

            u64 acc0[8], acc1[8];
            #pragma unroll
            for (int r = 0; r < 8; r++) { acc0[r] = 0ull; acc1[r] = 0ull; }

            const int kp0 = ks * 48;
            #pragma unroll 4
            for (int kp = kp0; kp < kp0 + 48; kp += 2) {
                ulonglong2 w0 = *(const ulonglong2*)(w5p + (size_t)kp*128 + 2*q);
                ulonglong2 w1 = *(const ulonglong2*)(w5p + (size_t)(kp + 1)*128 + 2*q);
                const int k4 = kp * 2;
                #pragma unroll
                for (int r = 0; r < 8; r++) {
                    ulonglong2 sv = *(const ulonglong2*)(skp + r*384 + k4);
                    fma2(acc0[r], sv.x, w0.x); fma2(acc1[r], sv.x, w0.y);
                    fma2(acc0[r], sv.y, w1.x); fma2(acc1[r], sv.y, w1.y);
                }
            }
            #pragma unroll
            for (int r = 0; r < 8; r++)
                *(float2*)(wp + ks*1024 + r*128 + 2*q) =
                    make_float2(sum2(acc0[r]), sum2(acc1[r]));
        }
        __syncthreads();

        // ---- Phase F: reduce 4 partials, + b5, relu ----
        #pragma unroll
        for (int o = tid; o < 1024; o += NT)
            hsm[o] = fmaxf(wp[o] + wp[1024 + o] + wp[2048 + o] + wp[3072 + o]
                           + sm[OFF_B5 + (o & 127)], 0.0f);
        __syncthreads();

        // ---- Phase G: y = h @ W6 + b6 (one warp per row) ----
        {
            const int w = tid >> 5, lane = tid & 31;
            float v = hsm[w*128 + lane]      * sm[OFF_W6 + lane]
                    + hsm[w*128 + 32 + lane] * sm[OFF_W6 + 32 + lane]
                    + hsm[w*128 + 64 + lane] * sm[OFF_W6 + 64 + lane]
                    + hsm[w*128 + 96 + lane] * sm[OFF_W6 + 96 + lane];
            #pragma unroll
            for (int off = 16; off; off >>= 1)
                v += __shfl_down_sync(0xffffffffu, v, off);
            if (lane == 0) {
                float y = v + sm[OFF_B6];
                pv[w] = y;
                out[(size_t)(row0 + w)*T_PRED + t] = y;
            }
        }
        __syncthreads();
    }
}

extern "C" void kernel_launch(void* const* d_in, const int* in_sizes, int n_in,
                              void* d_out, int out_size) {
    const float* feat = (const float*)d_in[0];
    const float* init = (const float*)d_in[1];
    const float* enc  = (const float*)d_in[2];
    const float* W1 = (const float*)d_in[3];
    const float* b1 = (const float*)d_in[4];
    const float* W2 = (const float*)d_in[5];
    const float* b2 = (const float*)d_in[6];
    const float* W3 = (const float*)d_in[7];
    const float* W4 = (const float*)d_in[8];
    const float* b4 = (const float*)d_in[9];
    const float* W5 = (const float*)d_in[10];
    const float* b5 = (const float*)d_in[11];
    const float* W6 = (const float*)d_in[12];
    const float* b6 = (const float*)d_in[13];
    float* outp = (float*)d_out;

    w5_pack_kernel<<<48, 1024>>>(W5);

    const size_t smem_bytes = (size_t)SMEM_FLOATS * sizeof(float);
    cudaFuncSetAttribute(decoder_kernel,
                         cudaFuncAttributeMaxDynamicSharedMemorySize,
                         (int)smem_bytes);
    decoder_kernel<<<NBLK, NT, smem_bytes>>>(feat, init, enc,
                                             W1, b1, W2, b2, W3, W4, b4,
                                             b5, W6, b6, outp);
}